// round 8
// baseline (speedup 1.0000x reference)
#include <cuda_runtime.h>
#include <cuda_fp16.h>
#include <math.h>
#include <stdint.h>

#define NE 50000
#define NN 25000
#define NG 1024
#define HID 128
#define NTILES 391
#define HA_STRIDE ((size_t)NTILES * 32768)

// smem layout (dynamic): A [128x272B] | B buf0 [64x272B] | B buf1
#define SM_B      34816          // 128*272
#define SM_BUF    17408          // 64*272
#define SMEM_BYTES 69632

__device__ __align__(256) unsigned char g_hA[3 * HA_STRIDE];  // per-layer, per-tile fp16 h [128x256B]
__device__ __align__(256) unsigned char g_w2s[103 * 16384];   // all layers' fp16 w2T chunks [64x256B]
__device__ float g_fa[NN * 64];
__device__ float g_fb[NN * 64];
__device__ float g_acc[NN * 64];
__device__ float g_y[NN * 64];        // x @ b2 per node
__device__ float g_sums[NG * 64];
__device__ float g_cnt[NG];
__device__ int g_src[NE], g_dst[NE], g_batch[NN], g_is64;

__device__ __forceinline__ float eluf(float v) { return v > 0.f ? v : expm1f(v); }
__device__ __forceinline__ uint32_t s2u(const void* p) {
    uint32_t a;
    asm("{ .reg .u64 t; cvta.to.shared.u64 t, %1; cvt.u32.u64 %0, t; }" : "=r"(a) : "l"(p));
    return a;
}
__device__ __forceinline__ void cp16(uint32_t s, const void* g) {
    asm volatile("cp.async.cg.shared.global [%0], [%1], 16;" :: "r"(s), "l"(g));
}
__device__ __forceinline__ void cp_commit() { asm volatile("cp.async.commit_group;" ::: "memory"); }
template<int N> __device__ __forceinline__ void cp_wait() { asm volatile("cp.async.wait_group %0;" :: "n"(N) : "memory"); }
__device__ __forceinline__ void ldsm4(uint32_t* r, uint32_t a) {
    asm volatile("ldmatrix.sync.aligned.m8n8.x4.shared.b16 {%0,%1,%2,%3}, [%4];"
                 : "=r"(r[0]), "=r"(r[1]), "=r"(r[2]), "=r"(r[3]) : "r"(a));
}
__device__ __forceinline__ void mma16816(float* d, const uint32_t* a, uint32_t b0, uint32_t b1) {
    asm volatile("mma.sync.aligned.m16n8k16.row.col.f32.f16.f16.f32 "
                 "{%0,%1,%2,%3}, {%4,%5,%6,%7}, {%8,%9}, {%0,%1,%2,%3};"
                 : "+f"(d[0]), "+f"(d[1]), "+f"(d[2]), "+f"(d[3])
                 : "r"(a[0]), "r"(a[1]), "r"(a[2]), "r"(a[3]), "r"(b0), "r"(b1));
}

// ---------------- index dtype detect + convert -----------------------------
__global__ void detect_kernel(const long long* __restrict__ ei) {
    if (blockIdx.x == 0 && threadIdx.x == 0) {
        int is64 = 1;
        for (int i = 0; i < 256; i++) { long long v = ei[i]; if (v < 0 || v >= (long long)NN) { is64 = 0; break; } }
        g_is64 = is64;
    }
}
__global__ void convert_kernel(const void* __restrict__ ei, const void* __restrict__ bat) {
    int t = blockIdx.x * blockDim.x + threadIdx.x;
    const int is64 = g_is64;
    if (t < NE) {
        if (is64) { g_src[t] = (int)((const long long*)ei)[t]; g_dst[t] = (int)((const long long*)ei)[NE + t]; }
        else      { g_src[t] = ((const int*)ei)[t];            g_dst[t] = ((const int*)ei)[NE + t]; }
    }
    if (t < NN) g_batch[t] = is64 ? (int)((const long long*)bat)[t] : ((const int*)bat)[t];
}

__global__ void pool_init_kernel() {
    int t = blockIdx.x * blockDim.x + threadIdx.x;
    if (t < NG * 64) g_sums[t] = 0.f;
    if (t < NG) g_cnt[t] = 0.f;
}

// -------- edge MLP for ALL 3 layers -> fp16 A tiles (ea read once) ---------
__global__ void edge_hA3_kernel(const float* __restrict__ ea,
                                const float* __restrict__ w1a, const float* __restrict__ b1a,
                                const float* __restrict__ w1b, const float* __restrict__ b1b,
                                const float* __restrict__ w1c, const float* __restrict__ b1c) {
    int t = blockIdx.x * blockDim.x + threadIdx.x;
    if (t >= NE * 64) return;
    int e = t >> 6, k = (t & 63) * 2;
    const float* ar = ea + e * 5;
    float a0 = ar[0], a1 = ar[1], a2 = ar[2], a3 = ar[3], a4 = ar[4];
    int tile = e >> 7, row = e & 127;
    uint32_t off = (uint32_t)(row * 256 + k * 2);
    unsigned char* base = g_hA + (size_t)tile * 32768 + off;

    const float* w1s[3] = { w1a, w1b, w1c };
    const float* b1s[3] = { b1a, b1b, b1c };
#pragma unroll
    for (int L = 0; L < 3; L++) {
        const float* w1 = w1s[L];
        float s0 = b1s[L][k], s1 = b1s[L][k + 1];
        s0 = fmaf(a0, w1[0 * HID + k], s0); s1 = fmaf(a0, w1[0 * HID + k + 1], s1);
        s0 = fmaf(a1, w1[1 * HID + k], s0); s1 = fmaf(a1, w1[1 * HID + k + 1], s1);
        s0 = fmaf(a2, w1[2 * HID + k], s0); s1 = fmaf(a2, w1[2 * HID + k + 1], s1);
        s0 = fmaf(a3, w1[3 * HID + k], s0); s1 = fmaf(a3, w1[3 * HID + k + 1], s1);
        s0 = fmaf(a4, w1[4 * HID + k], s0); s1 = fmaf(a4, w1[4 * HID + k + 1], s1);
        s0 = fmaxf(s0, 0.f); s1 = fmaxf(s1, 0.f);
        __half h0 = __float2half(s0), h1 = __float2half(s1);
        *(uint32_t*)(base + L * HA_STRIDE) =
            ((uint32_t)__half_as_ushort(h1) << 16) | __half_as_ushort(h0);
    }
}

// -------- w2 -> fp16 B chunk tiles at a given chunk base -------------------
template<int M_IN, int M_OUT, int NC, int CBASE>
__global__ void w2prep_kernel(const float* __restrict__ w2) {
    int t = blockIdx.x * blockDim.x + threadIdx.x;
    if (t >= NC * 8192) return;
    int c = t >> 13, rem = t & 8191, r = rem >> 7, k = rem & 127;
    int n = c * 64 + r;
    float v = (n < M_IN * M_OUT) ? w2[k * (M_IN * M_OUT) + n] : 0.f;
    *(__half*)(g_w2s + (size_t)(CBASE + c) * 16384 + r * 256 + k * 2) = __float2half(v);
}

// -------- acc = x @ root + bias;  g_y = x @ b2  (fused, one x-row read) ----
template<int M_IN, int M_OUT>
__global__ void rootxb2_kernel(const float* __restrict__ x, const float* __restrict__ root,
                               const float* __restrict__ bias, const float* __restrict__ b2,
                               float* __restrict__ acc) {
    int t = blockIdx.x * blockDim.x + threadIdx.x;
    if (t >= NN * M_OUT) return;
    int n = t / M_OUT, o = t - n * M_OUT;
    const float* xr = x + n * M_IN;
    float s = bias[o], y = 0.f;
#pragma unroll
    for (int i = 0; i < M_IN; i++) {
        float xv = xr[i];
        s = fmaf(xv, root[i * M_OUT + o], s);
        y = fmaf(xv, b2[i * M_OUT + o], y);
    }
    acc[t] = s;
    g_y[t] = y;
}

__global__ void elu_kernel(const float* __restrict__ acc, float* __restrict__ xo, int n) {
    int t = blockIdx.x * blockDim.x + threadIdx.x;
    if (t < n) xo[t] = eluf(acc[t]);
}

// -------- layer-3 elu fused with graph pooling (features never stored) -----
__global__ void elu_pool_kernel(const float* __restrict__ acc) {
    int t = blockIdx.x * blockDim.x + threadIdx.x;
    if (t >= NN * 64) return;
    int n = t >> 6, o = t & 63;
    float v = eluf(acc[t]);
    int g = g_batch[n];
    atomicAdd(&g_sums[g * 64 + o], v);
    if (o == 0) atomicAdd(&g_cnt[g], 1.f);
}

// -------- message GEMM (fp16 mma) + contract + scatter ---------------------
// Chunk dimension split NSPLIT ways across CTAs (atomicAdd merges partials;
// the x@b2 term is added by split 0 only) to cut wave-quantization tail:
// 391 CTAs @ 296 concurrent = 1.32 waves (34% idle) -> 782 CTAs = 2.64 waves.
__device__ __forceinline__ void copyB(int cabs, uint32_t dst, int tid) {
    const unsigned char* gb = g_w2s + (size_t)cabs * 16384;
    for (int idx = tid; idx < 1024; idx += 256) {
        int r = idx >> 4, s = idx & 15;
        cp16(dst + r * 272 + s * 16, gb + r * 256 + s * 16);
    }
}

template<int M_IN, int M_OUT, int NC_TOT, int NSPLIT, int CBASE>
__global__ void __launch_bounds__(256, 2)
msg_mma_kernel(const float* __restrict__ xin, float* __restrict__ acc,
               const unsigned char* __restrict__ hA) {
    constexpr int NC = NC_TOT / NSPLIT;
    extern __shared__ char smem[];
    const uint32_t sb = s2u(smem);
    const int tid = threadIdx.x, wid = tid >> 5, lane = tid & 31;
    const int tile  = blockIdx.x / NSPLIT;
    const int split = blockIdx.x - tile * NSPLIT;
    const int c0    = CBASE + split * NC;

    // prologue: A + B0 as group0; B1 as group1
    {
        const unsigned char* ga = hA + (size_t)tile * 32768;
        for (int idx = tid; idx < 2048; idx += 256) {
            int r = (idx >> 4) & 127, s = idx & 15;
            cp16(sb + r * 272 + s * 16, ga + r * 256 + s * 16);
        }
        copyB(c0, sb + SM_B, tid);
        cp_commit();
        if (NC > 1) { copyB(c0 + 1, sb + SM_B + SM_BUF, tid); cp_commit(); }
    }

    const int m0 = wid * 16;
    const int r0 = lane >> 2;
    const int e0 = tile * 128 + m0 + r0;
    const int e1 = e0 + 8;
    int src0 = 0, dst0 = -1, src1 = 0, dst1 = -1;
    if (e0 < NE) { src0 = g_src[e0]; dst0 = g_dst[e0]; }
    if (e1 < NE) { src1 = g_src[e1]; dst1 = g_dst[e1]; }

    const uint32_t lrow = (lane & 15);
    const uint32_t kh16 = (lane >> 4) * 16;

    float av[8][4];
#pragma unroll
    for (int nb = 0; nb < 8; nb++)
#pragma unroll
        for (int q = 0; q < 4; q++) av[nb][q] = 0.f;

    for (int c = 0; c < NC; c++) {
        if (c + 1 == NC) cp_wait<0>(); else cp_wait<1>();
        __syncthreads();

        const uint32_t Bb = sb + SM_B + (uint32_t)(c & 1) * SM_BUF;
        float d[8][4];
#pragma unroll
        for (int nb = 0; nb < 8; nb++)
#pragma unroll
            for (int q = 0; q < 4; q++) d[nb][q] = 0.f;

#pragma unroll
        for (int ks = 0; ks < 8; ks++) {
            uint32_t a[4];
            ldsm4(a, sb + (m0 + lrow) * 272 + ks * 32 + kh16);
#pragma unroll
            for (int nb2 = 0; nb2 < 4; nb2++) {
                uint32_t b[4];
                ldsm4(b, Bb + (nb2 * 16 + lrow) * 272 + ks * 32 + kh16);
                mma16816(d[2 * nb2],     a, b[0], b[2]);
                mma16816(d[2 * nb2 + 1], a, b[1], b[3]);
            }
        }

        // contract chunk with fp32 x (absolute chunk index within layer)
        const int ca = split * NC + c;
        if constexpr (M_OUT == 64) {
            const float xs0 = xin[(size_t)src0 * M_IN + ca];
            const float xs1 = xin[(size_t)src1 * M_IN + ca];
#pragma unroll
            for (int nb = 0; nb < 8; nb++) {
                av[nb][0] = fmaf(xs0, d[nb][0], av[nb][0]);
                av[nb][1] = fmaf(xs0, d[nb][1], av[nb][1]);
                av[nb][2] = fmaf(xs1, d[nb][2], av[nb][2]);
                av[nb][3] = fmaf(xs1, d[nb][3], av[nb][3]);
            }
        } else {
            const int i0 = min(2 * ca, M_IN - 1), i1 = min(2 * ca + 1, M_IN - 1);
            const float x00 = xin[(size_t)src0 * M_IN + i0];
            const float x01 = xin[(size_t)src0 * M_IN + i1];
            const float x10 = xin[(size_t)src1 * M_IN + i0];
            const float x11 = xin[(size_t)src1 * M_IN + i1];
#pragma unroll
            for (int nb = 0; nb < 8; nb++) {
                const float xsa = (nb < 4) ? x00 : x01;
                const float xsb = (nb < 4) ? x10 : x11;
                av[nb][0] = fmaf(xsa, d[nb][0], av[nb][0]);
                av[nb][1] = fmaf(xsa, d[nb][1], av[nb][1]);
                av[nb][2] = fmaf(xsb, d[nb][2], av[nb][2]);
                av[nb][3] = fmaf(xsb, d[nb][3], av[nb][3]);
            }
        }

        __syncthreads();                 // all warps done reading buf before refill
        if (c + 2 < NC) { copyB(c0 + c + 2, sb + SM_B + (uint32_t)(c & 1) * SM_BUF, tid); cp_commit(); }
    }

    // scatter-add (+ x@b2 term, added by split 0 only)
    const bool addy = (split == 0);
    const int oc = (lane & 3) * 2;
    if constexpr (M_OUT == 64) {
#pragma unroll
        for (int nb = 0; nb < 8; nb++) {
            const int o = nb * 8 + oc;
            if (dst0 >= 0) {
                float y0 = addy ? g_y[(size_t)src0 * 64 + o]     : 0.f;
                float y1 = addy ? g_y[(size_t)src0 * 64 + o + 1] : 0.f;
                atomicAdd(acc + (size_t)dst0 * 64 + o,     av[nb][0] + y0);
                atomicAdd(acc + (size_t)dst0 * 64 + o + 1, av[nb][1] + y1);
            }
            if (dst1 >= 0) {
                float y0 = addy ? g_y[(size_t)src1 * 64 + o]     : 0.f;
                float y1 = addy ? g_y[(size_t)src1 * 64 + o + 1] : 0.f;
                atomicAdd(acc + (size_t)dst1 * 64 + o,     av[nb][2] + y0);
                atomicAdd(acc + (size_t)dst1 * 64 + o + 1, av[nb][3] + y1);
            }
        }
    } else {
#pragma unroll
        for (int nb = 0; nb < 4; nb++) {
            const int o = nb * 8 + oc;
            if (dst0 >= 0) {
                atomicAdd(acc + (size_t)dst0 * 32 + o,     av[nb][0] + av[nb + 4][0] + g_y[(size_t)src0 * 32 + o]);
                atomicAdd(acc + (size_t)dst0 * 32 + o + 1, av[nb][1] + av[nb + 4][1] + g_y[(size_t)src0 * 32 + o + 1]);
            }
            if (dst1 >= 0) {
                atomicAdd(acc + (size_t)dst1 * 32 + o,     av[nb][2] + av[nb + 4][2] + g_y[(size_t)src1 * 32 + o]);
                atomicAdd(acc + (size_t)dst1 * 32 + o + 1, av[nb][3] + av[nb + 4][3] + g_y[(size_t)src1 * 32 + o + 1]);
            }
        }
    }
}

// ---------------- final MLP -------------------------------------------------
__global__ void __launch_bounds__(128)
mlp_kernel(const float* __restrict__ f1w, const float* __restrict__ f1b,
           const float* __restrict__ f2w, const float* __restrict__ f2b,
           const float* __restrict__ f3w, const float* __restrict__ f3b,
           float* __restrict__ out) {
    int g = blockIdx.x * blockDim.x + threadIdx.x;
    if (g >= NG) return;
    float inv = 1.f / fmaxf(g_cnt[g], 1.f);
    const float* sr = g_sums + g * 64;
    float h1[32];
#pragma unroll
    for (int j = 0; j < 32; j++) {
        float s = 0.f;
#pragma unroll
        for (int i = 0; i < 64; i++) s = fmaf(sr[i], f1w[i * 32 + j], s);
        h1[j] = eluf(fmaf(s, inv, f1b[j]));
    }
    float h2[16];
#pragma unroll
    for (int j = 0; j < 16; j++) {
        float s = f2b[j];
#pragma unroll
        for (int i = 0; i < 32; i++) s = fmaf(h1[i], f2w[i * 16 + j], s);
        h2[j] = eluf(s);
    }
    float s = f3b[0];
#pragma unroll
    for (int i = 0; i < 16; i++) s = fmaf(h2[i], f3w[i], s);
    out[g] = s;
}

// ---------------- driver ----------------------------------------------------
extern "C" void kernel_launch(void* const* d_in, const int* in_sizes, int n_in,
                              void* d_out, int out_size) {
    const float* x   = (const float*)d_in[0];
    const void*  ei  = d_in[1];
    const float* ea  = (const float*)d_in[2];
    const void*  bat = d_in[3];
    const float* W[24];
    for (int i = 0; i < 24; i++) W[i] = (const float*)d_in[4 + i];
    float* out = (float*)d_out;

    float *fa, *fb, *acc;
    unsigned char* hA;
    cudaGetSymbolAddress((void**)&fa, g_fa);
    cudaGetSymbolAddress((void**)&fb, g_fb);
    cudaGetSymbolAddress((void**)&acc, g_acc);
    cudaGetSymbolAddress((void**)&hA, g_hA);

    cudaFuncSetAttribute(msg_mma_kernel<13, 32, 7, 1, 0>,   cudaFuncAttributeMaxDynamicSharedMemorySize, SMEM_BYTES);
    cudaFuncSetAttribute(msg_mma_kernel<32, 64, 32, 2, 7>,  cudaFuncAttributeMaxDynamicSharedMemorySize, SMEM_BYTES);
    cudaFuncSetAttribute(msg_mma_kernel<64, 64, 64, 2, 39>, cudaFuncAttributeMaxDynamicSharedMemorySize, SMEM_BYTES);

    detect_kernel<<<1, 32>>>((const long long*)ei);
    convert_kernel<<<(NE + 255) / 256, 256>>>(ei, bat);
    pool_init_kernel<<<(NG * 64 + 255) / 256, 256>>>();

    // all prep up front
    edge_hA3_kernel<<<(NE * 64 + 255) / 256, 256>>>(ea, W[0], W[1], W[6], W[7], W[12], W[13]);
    w2prep_kernel<13, 32, 7, 0>  <<<(7 * 8192 + 255) / 256, 256>>>(W[2]);
    w2prep_kernel<32, 64, 32, 7> <<<(32 * 8192 + 255) / 256, 256>>>(W[8]);
    w2prep_kernel<64, 64, 64, 39><<<(64 * 8192 + 255) / 256, 256>>>(W[14]);

    // layer 1: 13 -> 32
    rootxb2_kernel<13, 32><<<(NN * 32 + 255) / 256, 256>>>(x, W[4], W[5], W[3], acc);
    msg_mma_kernel<13, 32, 7, 1, 0><<<NTILES, 256, SMEM_BYTES>>>(x, acc, hA);
    elu_kernel<<<(NN * 32 + 255) / 256, 256>>>(acc, fa, NN * 32);

    // layer 2: 32 -> 64 (chunk-split x2)
    rootxb2_kernel<32, 64><<<(NN * 64 + 255) / 256, 256>>>(fa, W[10], W[11], W[9], acc);
    msg_mma_kernel<32, 64, 32, 2, 7><<<NTILES * 2, 256, SMEM_BYTES>>>(fa, acc, hA + HA_STRIDE);
    elu_kernel<<<(NN * 64 + 255) / 256, 256>>>(acc, fb, NN * 64);

    // layer 3: 64 -> 64 (chunk-split x2; elu fused with pooling)
    rootxb2_kernel<64, 64><<<(NN * 64 + 255) / 256, 256>>>(fb, W[16], W[17], W[15], acc);
    msg_mma_kernel<64, 64, 64, 2, 39><<<NTILES * 2, 256, SMEM_BYTES>>>(fb, acc, hA + 2 * HA_STRIDE);
    elu_pool_kernel<<<(NN * 64 + 255) / 256, 256>>>(acc);

    // head
    mlp_kernel<<<(NG + 127) / 128, 128>>>(W[18], W[19], W[20], W[21], W[22], W[23], out);
}